// round 3
// baseline (speedup 1.0000x reference)
#include <cuda_runtime.h>

#define FULL 0xFFFFFFFFu

// Precomputed v[i,d] = sum_e W_bil[d,e] * item_table[i,e]  (NI=50000, D=32)
__device__ float g_vtab[50000 * 32];
// Mask dtype mode: 0 = int32, 1 = float32, 2 = uint8 (packed bytes)
__device__ int g_mask_mode;

// ---------------------------------------------------------------------------
// Precompute kernel: one warp per item row. W_bil transposed into padded smem.
// Thread (0,0) also sniffs the member_mask dtype from its first 32-bit word:
// mask[0,0] is guaranteed true (lengths >= 1).
// ---------------------------------------------------------------------------
__global__ void __launch_bounds__(256) vtab_kernel(
    const float* __restrict__ W_bil,
    const float* __restrict__ item_table,
    const unsigned int* __restrict__ mask_words,
    int NI)
{
    __shared__ float WT[32 * 33];   // WT[e*33 + d] = W_bil[d*32 + e]
    int t = threadIdx.x;

    if (blockIdx.x == 0 && t == 0) {
        unsigned int w0 = mask_words[0];
        int mode;
        if (w0 == 1u)               mode = 0;  // int32 bool
        else if (w0 == 0x3F800000u) mode = 1;  // float32 bool
        else                        mode = 2;  // uint8 bytes (e.g. 0x00000101)
        g_mask_mode = mode;
    }

    for (int k = t; k < 1024; k += blockDim.x) {
        int d = k >> 5, e = k & 31;
        WT[e * 33 + d] = W_bil[k];
    }
    __syncthreads();

    int warp = t >> 5, lane = t & 31;
    int i = blockIdx.x * (blockDim.x >> 5) + warp;
    if (i >= NI) return;

    float x = item_table[i * 32 + lane];
    float v = 0.f;
    #pragma unroll
    for (int e = 0; e < 32; e++) {
        v = fmaf(WT[e * 33 + lane], __shfl_sync(FULL, x, e), v);
    }
    g_vtab[i * 32 + lane] = v;
}

// ---------------------------------------------------------------------------
// Main kernel: one warp per pair b (persistent grid-stride). lane = dim d.
// ---------------------------------------------------------------------------
__global__ void __launch_bounds__(256) bilinear_main_kernel(
    const int*           __restrict__ item_inputs,
    const int*           __restrict__ member_ids,
    const void*          __restrict__ member_mask,
    const float*         __restrict__ user_table,
    const float*         __restrict__ item_table,
    const float*         __restrict__ b_bil,
    const float*         __restrict__ W1,
    const float*         __restrict__ b1,
    const float*         __restrict__ W2,
    const float*         __restrict__ b2,
    float*               __restrict__ out,
    int B)
{
    const int lane   = threadIdx.x & 31;
    const int warp   = (blockIdx.x * blockDim.x + threadIdx.x) >> 5;
    const int nwarps = (gridDim.x * blockDim.x) >> 5;

    // Per-lane persistent MLP weights: lane l holds W1[j][l], W1[j][32+l], W1[j][64+l]
    float w1a[8], w1b[8], w1c[8];
    #pragma unroll
    for (int j = 0; j < 8; j++) {
        w1a[j] = W1[j * 96 +      lane];
        w1b[j] = W1[j * 96 + 32 + lane];
        w1c[j] = W1[j * 96 + 64 + lane];
    }
    const int   jsel = (lane >> 2) & 7;       // MLP-reduce ownership map
    const float b1c  = b1[jsel];
    const float w2c  = W2[jsel] * 0.25f;      // pre-divide for 4x lane replication
    const float bb   = b_bil[0];
    const float b2v  = b2[0];
    const int   mymem = (lane >> 1) & 15;     // member owned by this lane
    const int   mmode = g_mask_mode;          // uniform

    for (int b = warp; b < B; b += nwarps) {
        const int item = item_inputs[b];                        // broadcast load
        const float it_e = item_table[item * 32 + lane];
        const float v    = g_vtab  [item * 32 + lane];
        const int   mid  = member_ids [b * 16 + (lane & 15)];   // coalesced 64B

        bool mk;
        if (mmode == 0) {
            mk = ((const int*)member_mask)[b * 16 + mymem] != 0;
        } else if (mmode == 1) {
            mk = ((const float*)member_mask)[b * 16 + mymem] != 0.f;
        } else {
            mk = ((const unsigned char*)member_mask)[b * 16 + mymem] != 0;
        }

        // Gather 16 member rows; keep in registers (used twice).
        float me[16];
        #pragma unroll
        for (int m = 0; m < 16; m++) {
            const int idm = __shfl_sync(FULL, mid, m);
            me[m] = user_table[idm * 32 + lane];
        }

        // p[m] = me[m,lane] * v[lane]; multi-value butterfly reduce.
        // After reduce, lane l holds S_m for m = (l>>1)&15 (2x replication).
        float p[16];
        #pragma unroll
        for (int m = 0; m < 16; m++) p[m] = me[m] * v;

        float q[8];
        {
            const bool h = (lane & 16) != 0;
            #pragma unroll
            for (int i = 0; i < 8; i++) {
                const float keep = h ? p[i + 8] : p[i];
                const float send = h ? p[i]     : p[i + 8];
                q[i] = keep + __shfl_xor_sync(FULL, send, 16);
            }
        }
        float r[4];
        {
            const bool h = (lane & 8) != 0;
            #pragma unroll
            for (int i = 0; i < 4; i++) {
                const float keep = h ? q[i + 4] : q[i];
                const float send = h ? q[i]     : q[i + 4];
                r[i] = keep + __shfl_xor_sync(FULL, send, 8);
            }
        }
        float t2[2];
        {
            const bool h = (lane & 4) != 0;
            #pragma unroll
            for (int i = 0; i < 2; i++) {
                const float keep = h ? r[i + 2] : r[i];
                const float send = h ? r[i]     : r[i + 2];
                t2[i] = keep + __shfl_xor_sync(FULL, send, 4);
            }
        }
        float u;
        {
            const bool h = (lane & 2) != 0;
            const float keep = h ? t2[1] : t2[0];
            const float send = h ? t2[0] : t2[1];
            u = keep + __shfl_xor_sync(FULL, send, 2);
        }
        u += __shfl_xor_sync(FULL, u, 1);   // lane l now has full S for m=(l>>1)&15

        // mask + bias (reference: w = (s + b) * mask)
        const float w_own = mk ? (u + bb) : 0.f;

        // final_user[lane] = sum_m w_m * me[m][lane] ; broadcast each w from lane 2m
        float fu = 0.f;
        #pragma unroll
        for (int m = 0; m < 16; m++)
            fu = fmaf(__shfl_sync(FULL, w_own, 2 * m), me[m], fu);

        // MLP layer 1 partials: ne = [fu*it | fu | it]
        const float ne0 = fu * it_e;
        float part[8];
        #pragma unroll
        for (int j = 0; j < 8; j++)
            part[j] = fmaf(w1a[j], ne0, fmaf(w1b[j], fu, w1c[j] * it_e));

        // 8-value butterfly reduce: lane l ends with H_j for j = (l>>2)&7
        float qq[4];
        {
            const bool h = (lane & 16) != 0;
            #pragma unroll
            for (int i = 0; i < 4; i++) {
                const float keep = h ? part[i + 4] : part[i];
                const float send = h ? part[i]     : part[i + 4];
                qq[i] = keep + __shfl_xor_sync(FULL, send, 16);
            }
        }
        float rr[2];
        {
            const bool h = (lane & 8) != 0;
            #pragma unroll
            for (int i = 0; i < 2; i++) {
                const float keep = h ? qq[i + 2] : qq[i];
                const float send = h ? qq[i]     : qq[i + 2];
                rr[i] = keep + __shfl_xor_sync(FULL, send, 8);
            }
        }
        float uu;
        {
            const bool h = (lane & 4) != 0;
            const float keep = h ? rr[1] : rr[0];
            const float send = h ? rr[0] : rr[1];
            uu = keep + __shfl_xor_sync(FULL, send, 4);
        }
        uu += __shfl_xor_sync(FULL, uu, 2);
        uu += __shfl_xor_sync(FULL, uu, 1);   // H_{jsel}, replicated on 4 lanes

        // y = sigmoid(b2 + sum_j W2[j]*relu(H_j + b1[j])); w2c pre-divided by 4
        float tv = w2c * fmaxf(uu + b1c, 0.f);
        tv += __shfl_xor_sync(FULL, tv, 16);
        tv += __shfl_xor_sync(FULL, tv, 8);
        tv += __shfl_xor_sync(FULL, tv, 4);
        tv += __shfl_xor_sync(FULL, tv, 2);
        tv += __shfl_xor_sync(FULL, tv, 1);

        const float y = 1.f / (1.f + __expf(-(tv + b2v)));
        if (lane == 0) out[b] = y;
    }
}

// ---------------------------------------------------------------------------
extern "C" void kernel_launch(void* const* d_in, const int* in_sizes, int n_in,
                              void* d_out, int out_size)
{
    const int*           item_inputs = (const int*)          d_in[0];
    const int*           member_ids  = (const int*)          d_in[1];
    const void*          member_mask =                       d_in[2];
    const float*         user_table  = (const float*)        d_in[3];
    const float*         item_table  = (const float*)        d_in[4];
    const float*         W_bil       = (const float*)        d_in[5];
    const float*         b_bil       = (const float*)        d_in[6];
    const float*         W1          = (const float*)        d_in[7];
    const float*         b1          = (const float*)        d_in[8];
    const float*         W2          = (const float*)        d_in[9];
    const float*         b2          = (const float*)        d_in[10];
    float* out = (float*)d_out;

    const int B  = in_sizes[0];
    int NI = in_sizes[4] / 32;
    if (NI > 50000) NI = 50000;   // g_vtab capacity (problem spec: NI = 50000)

    vtab_kernel<<<(NI + 7) / 8, 256>>>(W_bil, item_table,
                                       (const unsigned int*)member_mask, NI);
    bilinear_main_kernel<<<1184, 256>>>(item_inputs, member_ids, member_mask,
                                        user_table, item_table,
                                        b_bil, W1, b1, W2, b2, out, B);
}

// round 4
// speedup vs baseline: 1.0560x; 1.0560x over previous
#include <cuda_runtime.h>

#define FULL 0xFFFFFFFFu

// Precomputed v[i,d] = sum_e W_bil[d,e] * item_table[i,e]  (NI=50000, D=32)
__device__ float g_vtab[50000 * 32];
// Mask dtype mode: 0 = int32, 1 = float32, 2 = uint8 (packed bytes)
__device__ int g_mask_mode;

// ---------------------------------------------------------------------------
// Precompute kernel: one warp per item row. W_bil transposed into padded smem.
// Thread (0,0) sniffs the member_mask dtype (mask[0,0] is guaranteed true).
// ---------------------------------------------------------------------------
__global__ void __launch_bounds__(256) vtab_kernel(
    const float* __restrict__ W_bil,
    const float* __restrict__ item_table,
    const unsigned int* __restrict__ mask_words,
    int NI)
{
    __shared__ float WT[32 * 33];
    int t = threadIdx.x;

    if (blockIdx.x == 0 && t == 0) {
        unsigned int w0 = mask_words[0];
        int mode;
        if (w0 == 1u)               mode = 0;  // int32 bool
        else if (w0 == 0x3F800000u) mode = 1;  // float32 bool
        else                        mode = 2;  // uint8 bytes
        g_mask_mode = mode;
    }

    for (int k = t; k < 1024; k += blockDim.x) {
        int d = k >> 5, e = k & 31;
        WT[e * 33 + d] = W_bil[k];
    }
    __syncthreads();

    int warp = t >> 5, lane = t & 31;
    int i = blockIdx.x * (blockDim.x >> 5) + warp;
    if (i >= NI) return;

    float x = item_table[i * 32 + lane];
    float v = 0.f;
    #pragma unroll
    for (int e = 0; e < 32; e++) {
        v = fmaf(WT[e * 33 + lane], __shfl_sync(FULL, x, e), v);
    }
    g_vtab[i * 32 + lane] = v;
}

// ---------------------------------------------------------------------------
// Main kernel: one warp per pair. lane = (g = lane>>3 member-group, c = lane&7
// dim-chunk). Each lane holds float4 (dims 4c..4c+3) of members 4*(i^tau)+g.
// All butterflies are select-free via XOR-permuted slot assignment.
// ---------------------------------------------------------------------------
__global__ void __launch_bounds__(256) bilinear_main_kernel(
    const int*           __restrict__ item_inputs,
    const int*           __restrict__ member_ids,
    const void*          __restrict__ member_mask,
    const float*         __restrict__ user_table,
    const float*         __restrict__ item_table,
    const float*         __restrict__ b_bil,
    const float*         __restrict__ W1,
    const float*         __restrict__ b1,
    const float*         __restrict__ W2,
    const float*         __restrict__ b2,
    float*               __restrict__ out,
    int B)
{
    const int lane   = threadIdx.x & 31;
    const int warp   = (blockIdx.x * blockDim.x + threadIdx.x) >> 5;
    const int nwarps = (gridDim.x * blockDim.x) >> 5;

    const int g   = lane >> 3;        // member group 0..3
    const int c   = lane & 7;         // dim chunk  0..7 (dims 4c..4c+3)
    const int tau = (c >> 1) & 3;     // slot XOR-permutation for score reduce
    const int rho = (c >> 2) & 1;     // slot XOR-permutation for MLP reduce

    // Slot member indices m_i = 4*(i^tau)+g and their shfl sources.
    const int t0 = 0 ^ tau, t1 = 1 ^ tau, t2 = 2 ^ tau, t3 = 3 ^ tau;
    const int sm0 = 4 * t0 + g, sm1 = 4 * t1 + g, sm2 = 4 * t2 + g, sm3 = 4 * t3 + g;
    const int sw0 = 8 * g + 2 * t0, sw1 = 8 * g + 2 * t1;   // owner lane of member m_i
    const int sw2 = 8 * g + 2 * t2, sw3 = 8 * g + 2 * t3;
    const int m_own = sm0;            // member owned by this lane after reduce

    // Per-lane persistent MLP weights, unit-permuted: slot u holds unit 2g+(u^rho).
    const int j0 = 2 * g + rho;       // owned unit (slot 0)
    const int j1 = 2 * g + (1 ^ rho); // slot 1
    float w1a[2][4], w1b[2][4], w1c[2][4];
    #pragma unroll
    for (int k = 0; k < 4; k++) {
        w1a[0][k] = W1[j0 * 96 +      4 * c + k];
        w1b[0][k] = W1[j0 * 96 + 32 + 4 * c + k];
        w1c[0][k] = W1[j0 * 96 + 64 + 4 * c + k];
        w1a[1][k] = W1[j1 * 96 +      4 * c + k];
        w1b[1][k] = W1[j1 * 96 + 32 + 4 * c + k];
        w1c[1][k] = W1[j1 * 96 + 64 + 4 * c + k];
    }
    const float b1c = b1[j0];
    const float w2c = W2[j0] * 0.25f;   // each unit replicated on 4 lanes
    const float bb  = b_bil[0];
    const float b2v = b2[0];
    const int   mmode = g_mask_mode;

    const float4* __restrict__ ut4 = (const float4*)user_table;
    const float4* __restrict__ it4p = (const float4*)item_table;
    const float4* __restrict__ vt4p = (const float4*)g_vtab;

    for (int b = warp; b < B; b += nwarps) {
        const int item = item_inputs[b];                      // uniform
        const float4 it4 = it4p[item * 8 + c];
        const float4 v4  = vt4p[item * 8 + c];
        const int mid = member_ids[b * 16 + (lane & 15)];     // coalesced

        bool mk;
        if (mmode == 0) {
            mk = ((const int*)member_mask)[b * 16 + m_own] != 0;
        } else if (mmode == 1) {
            mk = ((const float*)member_mask)[b * 16 + m_own] != 0.f;
        } else {
            mk = ((const unsigned char*)member_mask)[b * 16 + m_own] != 0;
        }

        // Gather 4 member rows (float4 each), slot i = member 4*(i^tau)+g.
        const int id0 = __shfl_sync(FULL, mid, sm0);
        const int id1 = __shfl_sync(FULL, mid, sm1);
        const int id2 = __shfl_sync(FULL, mid, sm2);
        const int id3 = __shfl_sync(FULL, mid, sm3);
        const float4 me0 = ut4[id0 * 8 + c];
        const float4 me1 = ut4[id1 * 8 + c];
        const float4 me2 = ut4[id2 * 8 + c];
        const float4 me3 = ut4[id3 * 8 + c];

        // Score partials: pp[i] = dot4(me_i, v4)  (member 4*(i^tau)+g, dims 4c..)
        float pp0 = fmaf(me0.x, v4.x, fmaf(me0.y, v4.y, fmaf(me0.z, v4.z, me0.w * v4.w)));
        float pp1 = fmaf(me1.x, v4.x, fmaf(me1.y, v4.y, fmaf(me1.z, v4.z, me1.w * v4.w)));
        float pp2 = fmaf(me2.x, v4.x, fmaf(me2.y, v4.y, fmaf(me2.z, v4.z, me2.w * v4.w)));
        float pp3 = fmaf(me3.x, v4.x, fmaf(me3.y, v4.y, fmaf(me3.z, v4.z, me3.w * v4.w)));

        // Select-free butterfly over the 8-lane c-group (xor 4, 2, 1).
        float q0 = pp0 + __shfl_xor_sync(FULL, pp2, 4);
        float q1 = pp1 + __shfl_xor_sync(FULL, pp3, 4);
        float s  = q0 + __shfl_xor_sync(FULL, q1, 2);
        s += __shfl_xor_sync(FULL, s, 1);
        // lane now owns s for member m_own = 4*tau+g (replicated on c^1).

        const float w_own = mk ? (s + bb) : 0.f;

        // fu partials: fu4 += w_{m_i} * me_i ; w broadcast from owner lane.
        const float w0 = __shfl_sync(FULL, w_own, sw0);
        const float w1 = __shfl_sync(FULL, w_own, sw1);
        const float w2 = __shfl_sync(FULL, w_own, sw2);
        const float w3 = __shfl_sync(FULL, w_own, sw3);

        float fx = w0 * me0.x, fy = w0 * me0.y, fz = w0 * me0.z, fw = w0 * me0.w;
        fx = fmaf(w1, me1.x, fx); fy = fmaf(w1, me1.y, fy);
        fz = fmaf(w1, me1.z, fz); fw = fmaf(w1, me1.w, fw);
        fx = fmaf(w2, me2.x, fx); fy = fmaf(w2, me2.y, fy);
        fz = fmaf(w2, me2.z, fz); fw = fmaf(w2, me2.w, fw);
        fx = fmaf(w3, me3.x, fx); fy = fmaf(w3, me3.y, fy);
        fz = fmaf(w3, me3.z, fz); fw = fmaf(w3, me3.w, fw);

        // Reduce fu over the 4 member groups (xor 8, 16); result replicated.
        fx += __shfl_xor_sync(FULL, fx, 8);  fy += __shfl_xor_sync(FULL, fy, 8);
        fz += __shfl_xor_sync(FULL, fz, 8);  fw += __shfl_xor_sync(FULL, fw, 8);
        fx += __shfl_xor_sync(FULL, fx, 16); fy += __shfl_xor_sync(FULL, fy, 16);
        fz += __shfl_xor_sync(FULL, fz, 16); fw += __shfl_xor_sync(FULL, fw, 16);

        // MLP layer 1: ne = fu*it. part[u] = unit 2g+(u^rho) partial over 4 dims.
        const float nx = fx * it4.x, ny = fy * it4.y, nz = fz * it4.z, nw = fw * it4.w;

        float part0, part1;
        {
            float a;
            a  = w1a[0][0] * nx + w1b[0][0] * fx + w1c[0][0] * it4.x;
            a += w1a[0][1] * ny + w1b[0][1] * fy + w1c[0][1] * it4.y;
            a += w1a[0][2] * nz + w1b[0][2] * fz + w1c[0][2] * it4.z;
            a += w1a[0][3] * nw + w1b[0][3] * fw + w1c[0][3] * it4.w;
            part0 = a;
            a  = w1a[1][0] * nx + w1b[1][0] * fx + w1c[1][0] * it4.x;
            a += w1a[1][1] * ny + w1b[1][1] * fy + w1c[1][1] * it4.y;
            a += w1a[1][2] * nz + w1b[1][2] * fz + w1c[1][2] * it4.z;
            a += w1a[1][3] * nw + w1b[1][3] * fw + w1c[1][3] * it4.w;
            part1 = a;
        }

        // Select-free MLP reduce over c (xor 4, 2, 1): lane owns H_{j0}.
        float h = part0 + __shfl_xor_sync(FULL, part1, 4);
        h += __shfl_xor_sync(FULL, h, 2);
        h += __shfl_xor_sync(FULL, h, 1);

        // Output layer: tv = W2[j0]/4 * relu(H + b1); full-warp sum.
        float tv = w2c * fmaxf(h + b1c, 0.f);
        tv += __shfl_xor_sync(FULL, tv, 16);
        tv += __shfl_xor_sync(FULL, tv, 8);
        tv += __shfl_xor_sync(FULL, tv, 4);
        tv += __shfl_xor_sync(FULL, tv, 2);
        tv += __shfl_xor_sync(FULL, tv, 1);

        const float y = 1.f / (1.f + __expf(-(tv + b2v)));
        if (lane == 0) out[b] = y;
    }
}

// ---------------------------------------------------------------------------
extern "C" void kernel_launch(void* const* d_in, const int* in_sizes, int n_in,
                              void* d_out, int out_size)
{
    const int*   item_inputs = (const int*)  d_in[0];
    const int*   member_ids  = (const int*)  d_in[1];
    const void*  member_mask =               d_in[2];
    const float* user_table  = (const float*)d_in[3];
    const float* item_table  = (const float*)d_in[4];
    const float* W_bil       = (const float*)d_in[5];
    const float* b_bil       = (const float*)d_in[6];
    const float* W1          = (const float*)d_in[7];
    const float* b1          = (const float*)d_in[8];
    const float* W2          = (const float*)d_in[9];
    const float* b2          = (const float*)d_in[10];
    float* out = (float*)d_out;

    const int B  = in_sizes[0];
    int NI = in_sizes[4] / 32;
    if (NI > 50000) NI = 50000;   // g_vtab capacity (problem spec: NI = 50000)

    vtab_kernel<<<(NI + 7) / 8, 256>>>(W_bil, item_table,
                                       (const unsigned int*)member_mask, NI);
    bilinear_main_kernel<<<1184, 256>>>(item_inputs, member_ids, member_mask,
                                        user_table, item_table,
                                        b_bil, W1, b1, W2, b2, out, B);
}

// round 5
// speedup vs baseline: 1.2380x; 1.1724x over previous
#include <cuda_runtime.h>

#define FULL 0xFFFFFFFFu

// Precomputed v[i,d] = sum_e W_bil[d,e] * item_table[i,e]  (NI=50000, D=32)
__device__ float g_vtab[50000 * 32];
// Mask dtype mode: 0 = int32, 1 = float32, 2 = uint8 (packed bytes)
__device__ int g_mask_mode;

// ---------------------------------------------------------------------------
// Precompute kernel: one warp per item row. W_bil transposed into padded smem.
// Thread (0,0) sniffs the member_mask dtype (mask[0,0] is guaranteed true).
// ---------------------------------------------------------------------------
__global__ void __launch_bounds__(256) vtab_kernel(
    const float* __restrict__ W_bil,
    const float* __restrict__ item_table,
    const unsigned int* __restrict__ mask_words,
    int NI)
{
    __shared__ float WT[32 * 33];
    int t = threadIdx.x;

    if (blockIdx.x == 0 && t == 0) {
        unsigned int w0 = mask_words[0];
        int mode;
        if (w0 == 1u)               mode = 0;  // int32 bool
        else if (w0 == 0x3F800000u) mode = 1;  // float32 bool
        else                        mode = 2;  // uint8 bytes
        g_mask_mode = mode;
    }

    for (int k = t; k < 1024; k += blockDim.x) {
        int d = k >> 5, e = k & 31;
        WT[e * 33 + d] = W_bil[k];
    }
    __syncthreads();

    int warp = t >> 5, lane = t & 31;
    int i = blockIdx.x * (blockDim.x >> 5) + warp;
    if (i >= NI) return;

    float x = item_table[i * 32 + lane];
    float v = 0.f;
    #pragma unroll
    for (int e = 0; e < 32; e++) {
        v = fmaf(WT[e * 33 + lane], __shfl_sync(FULL, x, e), v);
    }
    g_vtab[i * 32 + lane] = v;
}

__device__ __forceinline__ float dot4(const float4 a, const float4 b) {
    return fmaf(a.x, b.x, fmaf(a.y, b.y, fmaf(a.z, b.z, a.w * b.w)));
}

// ---------------------------------------------------------------------------
// Main kernel: one warp handles TWO pairs per iteration (ILP=2), each pair
// decomposed over all 32 lanes as (g = lane>>3 member-group, c = lane&7
// dim-chunk of float4). Select-free butterflies via XOR-permuted slots.
// W1 lives in shared memory, reloaded per iteration (asm volatile) to keep
// register count low enough for 3 CTAs/SM.
// ---------------------------------------------------------------------------
__global__ void __launch_bounds__(256, 3) bilinear_main_kernel(
    const int*           __restrict__ item_inputs,
    const int*           __restrict__ member_ids,
    const void*          __restrict__ member_mask,
    const float*         __restrict__ user_table,
    const float*         __restrict__ item_table,
    const float*         __restrict__ b_bil,
    const float*         __restrict__ W1,
    const float*         __restrict__ b1,
    const float*         __restrict__ W2,
    const float*         __restrict__ b2,
    float*               __restrict__ out,
    int B)
{
    __shared__ float w1s[768];      // W1 [8][96]
    for (int k = threadIdx.x; k < 768; k += 256) w1s[k] = W1[k];
    __syncthreads();

    const int lane   = threadIdx.x & 31;
    const int warp   = (blockIdx.x * blockDim.x + threadIdx.x) >> 5;
    const int nwarps = (gridDim.x * blockDim.x) >> 5;

    const int g   = lane >> 3;        // member group 0..3
    const int c   = lane & 7;         // dim chunk 0..7 (dims 4c..4c+3)
    const int tau = (c >> 1) & 3;
    const int rho = (c >> 2) & 1;

    const int t0 = tau, t1 = 1 ^ tau, t2 = 2 ^ tau, t3 = 3 ^ tau;
    const int sm0 = 4 * t0 + g, sm1 = 4 * t1 + g, sm2 = 4 * t2 + g, sm3 = 4 * t3 + g;
    const int sw0 = 8 * g + 2 * t0, sw1 = 8 * g + 2 * t1;
    const int sw2 = 8 * g + 2 * t2, sw3 = 8 * g + 2 * t3;
    const int m_own = sm0;

    const int j0 = 2 * g + rho;
    const int j1 = 2 * g + (1 ^ rho);

    const float b1c = b1[j0];
    const float w2c = W2[j0] * 0.25f;
    const float bb  = b_bil[0];
    const float b2v = b2[0];
    const int   mmode = g_mask_mode;
    const int   half  = lane >> 4;    // 0 -> pair A, 1 -> pair B for shared loads

    const unsigned w1_0 = (unsigned)__cvta_generic_to_shared(&w1s[j0 * 96 + 4 * c]);
    const unsigned w1_1 = (unsigned)__cvta_generic_to_shared(&w1s[j1 * 96 + 4 * c]);

    const float4* __restrict__ ut4  = (const float4*)user_table;
    const float4* __restrict__ it4p = (const float4*)item_table;
    const float4* __restrict__ vt4p = (const float4*)g_vtab;

    for (int base = 2 * warp; base < B; base += 2 * nwarps) {
        const int bA = base;
        const int bB = (base + 1 < B) ? base + 1 : base;

        const int itmA = item_inputs[bA];
        const int itmB = item_inputs[bB];
        const float4 itA = it4p[itmA * 8 + c];
        const float4 vA  = vt4p[itmA * 8 + c];
        const float4 itB = it4p[itmB * 8 + c];
        const float4 vB  = vt4p[itmB * 8 + c];

        // One 128B load serves both pairs' member ids (lanes 0-15: A, 16-31: B)
        const int bH  = half ? bB : bA;
        const int mid = member_ids[bH * 16 + (lane & 15)];

        bool mkA, mkB;
        if (mmode == 0) {
            const int mw = ((const int*)member_mask)[bH * 16 + (lane & 15)];
            mkA = __shfl_sync(FULL, mw, m_own)      != 0;
            mkB = __shfl_sync(FULL, mw, 16 + m_own) != 0;
        } else if (mmode == 1) {
            mkA = ((const float*)member_mask)[bA * 16 + m_own] != 0.f;
            mkB = ((const float*)member_mask)[bB * 16 + m_own] != 0.f;
        } else {
            mkA = ((const unsigned char*)member_mask)[bA * 16 + m_own] != 0;
            mkB = ((const unsigned char*)member_mask)[bB * 16 + m_own] != 0;
        }

        // Member ids: pair A from lanes 0-15, pair B from lanes 16-31.
        const int a0 = __shfl_sync(FULL, mid, sm0);
        const int a1 = __shfl_sync(FULL, mid, sm1);
        const int a2 = __shfl_sync(FULL, mid, sm2);
        const int a3 = __shfl_sync(FULL, mid, sm3);
        const int e0 = __shfl_sync(FULL, mid, 16 + sm0);
        const int e1 = __shfl_sync(FULL, mid, 16 + sm1);
        const int e2 = __shfl_sync(FULL, mid, 16 + sm2);
        const int e3 = __shfl_sync(FULL, mid, 16 + sm3);

        const float4 mA0 = ut4[a0 * 8 + c];
        const float4 mA1 = ut4[a1 * 8 + c];
        const float4 mA2 = ut4[a2 * 8 + c];
        const float4 mA3 = ut4[a3 * 8 + c];
        const float4 mB0 = ut4[e0 * 8 + c];
        const float4 mB1 = ut4[e1 * 8 + c];
        const float4 mB2 = ut4[e2 * 8 + c];
        const float4 mB3 = ut4[e3 * 8 + c];

        // Score partials + select-free butterfly (xor 4, 2, 1) per pair.
        float pA0 = dot4(mA0, vA), pA1 = dot4(mA1, vA);
        float pA2 = dot4(mA2, vA), pA3 = dot4(mA3, vA);
        float pB0 = dot4(mB0, vB), pB1 = dot4(mB1, vB);
        float pB2 = dot4(mB2, vB), pB3 = dot4(mB3, vB);

        float qA0 = pA0 + __shfl_xor_sync(FULL, pA2, 4);
        float qA1 = pA1 + __shfl_xor_sync(FULL, pA3, 4);
        float qB0 = pB0 + __shfl_xor_sync(FULL, pB2, 4);
        float qB1 = pB1 + __shfl_xor_sync(FULL, pB3, 4);
        float sA = qA0 + __shfl_xor_sync(FULL, qA1, 2);
        float sB = qB0 + __shfl_xor_sync(FULL, qB1, 2);
        sA += __shfl_xor_sync(FULL, sA, 1);
        sB += __shfl_xor_sync(FULL, sB, 1);

        const float wOA = mkA ? (sA + bb) : 0.f;
        const float wOB = mkB ? (sB + bb) : 0.f;

        const float wA0 = __shfl_sync(FULL, wOA, sw0);
        const float wA1 = __shfl_sync(FULL, wOA, sw1);
        const float wA2 = __shfl_sync(FULL, wOA, sw2);
        const float wA3 = __shfl_sync(FULL, wOA, sw3);
        const float wB0 = __shfl_sync(FULL, wOB, sw0);
        const float wB1 = __shfl_sync(FULL, wOB, sw1);
        const float wB2 = __shfl_sync(FULL, wOB, sw2);
        const float wB3 = __shfl_sync(FULL, wOB, sw3);

        float fAx = wA0 * mA0.x, fAy = wA0 * mA0.y, fAz = wA0 * mA0.z, fAw = wA0 * mA0.w;
        fAx = fmaf(wA1, mA1.x, fAx); fAy = fmaf(wA1, mA1.y, fAy);
        fAz = fmaf(wA1, mA1.z, fAz); fAw = fmaf(wA1, mA1.w, fAw);
        fAx = fmaf(wA2, mA2.x, fAx); fAy = fmaf(wA2, mA2.y, fAy);
        fAz = fmaf(wA2, mA2.z, fAz); fAw = fmaf(wA2, mA2.w, fAw);
        fAx = fmaf(wA3, mA3.x, fAx); fAy = fmaf(wA3, mA3.y, fAy);
        fAz = fmaf(wA3, mA3.z, fAz); fAw = fmaf(wA3, mA3.w, fAw);

        float fBx = wB0 * mB0.x, fBy = wB0 * mB0.y, fBz = wB0 * mB0.z, fBw = wB0 * mB0.w;
        fBx = fmaf(wB1, mB1.x, fBx); fBy = fmaf(wB1, mB1.y, fBy);
        fBz = fmaf(wB1, mB1.z, fBz); fBw = fmaf(wB1, mB1.w, fBw);
        fBx = fmaf(wB2, mB2.x, fBx); fBy = fmaf(wB2, mB2.y, fBy);
        fBz = fmaf(wB2, mB2.z, fBz); fBw = fmaf(wB2, mB2.w, fBw);
        fBx = fmaf(wB3, mB3.x, fBx); fBy = fmaf(wB3, mB3.y, fBy);
        fBz = fmaf(wB3, mB3.z, fBz); fBw = fmaf(wB3, mB3.w, fBw);

        // Reduce fu over the 4 member groups (xor 8, 16); replicated result.
        fAx += __shfl_xor_sync(FULL, fAx, 8);  fAy += __shfl_xor_sync(FULL, fAy, 8);
        fAz += __shfl_xor_sync(FULL, fAz, 8);  fAw += __shfl_xor_sync(FULL, fAw, 8);
        fBx += __shfl_xor_sync(FULL, fBx, 8);  fBy += __shfl_xor_sync(FULL, fBy, 8);
        fBz += __shfl_xor_sync(FULL, fBz, 8);  fBw += __shfl_xor_sync(FULL, fBw, 8);
        fAx += __shfl_xor_sync(FULL, fAx, 16); fAy += __shfl_xor_sync(FULL, fAy, 16);
        fAz += __shfl_xor_sync(FULL, fAz, 16); fAw += __shfl_xor_sync(FULL, fAw, 16);
        fBx += __shfl_xor_sync(FULL, fBx, 16); fBy += __shfl_xor_sync(FULL, fBy, 16);
        fBz += __shfl_xor_sync(FULL, fBz, 16); fBw += __shfl_xor_sync(FULL, fBw, 16);

        // MLP layer 1. ne = fu*it.
        const float nAx = fAx * itA.x, nAy = fAy * itA.y;
        const float nAz = fAz * itA.z, nAw = fAw * itA.w;
        const float nBx = fBx * itB.x, nBy = fBy * itB.y;
        const float nBz = fBz * itB.z, nBw = fBw * itB.w;

        // Reload W1 slices from smem each iteration (volatile: not hoisted).
        float a00,a01,a02,a03, b00,b01,b02,b03, c00,c01,c02,c03;
        float a10,a11,a12,a13, b10,b11,b12,b13, c10,c11,c12,c13;
        asm volatile("ld.shared.v4.f32 {%0,%1,%2,%3},[%4];"
            : "=f"(a00),"=f"(a01),"=f"(a02),"=f"(a03) : "r"(w1_0));
        asm volatile("ld.shared.v4.f32 {%0,%1,%2,%3},[%4];"
            : "=f"(b00),"=f"(b01),"=f"(b02),"=f"(b03) : "r"(w1_0 + 128));
        asm volatile("ld.shared.v4.f32 {%0,%1,%2,%3},[%4];"
            : "=f"(c00),"=f"(c01),"=f"(c02),"=f"(c03) : "r"(w1_0 + 256));
        asm volatile("ld.shared.v4.f32 {%0,%1,%2,%3},[%4];"
            : "=f"(a10),"=f"(a11),"=f"(a12),"=f"(a13) : "r"(w1_1));
        asm volatile("ld.shared.v4.f32 {%0,%1,%2,%3},[%4];"
            : "=f"(b10),"=f"(b11),"=f"(b12),"=f"(b13) : "r"(w1_1 + 128));
        asm volatile("ld.shared.v4.f32 {%0,%1,%2,%3},[%4];"
            : "=f"(c10),"=f"(c11),"=f"(c12),"=f"(c13) : "r"(w1_1 + 256));

        float PA0, PA1, PB0, PB1;
        {
            float t;
            t = a00 * nAx; t = fmaf(b00, fAx, t); t = fmaf(c00, itA.x, t);
            t = fmaf(a01, nAy, t); t = fmaf(b01, fAy, t); t = fmaf(c01, itA.y, t);
            t = fmaf(a02, nAz, t); t = fmaf(b02, fAz, t); t = fmaf(c02, itA.z, t);
            t = fmaf(a03, nAw, t); t = fmaf(b03, fAw, t); t = fmaf(c03, itA.w, t);
            PA0 = t;
            t = a10 * nAx; t = fmaf(b10, fAx, t); t = fmaf(c10, itA.x, t);
            t = fmaf(a11, nAy, t); t = fmaf(b11, fAy, t); t = fmaf(c11, itA.y, t);
            t = fmaf(a12, nAz, t); t = fmaf(b12, fAz, t); t = fmaf(c12, itA.z, t);
            t = fmaf(a13, nAw, t); t = fmaf(b13, fAw, t); t = fmaf(c13, itA.w, t);
            PA1 = t;
            t = a00 * nBx; t = fmaf(b00, fBx, t); t = fmaf(c00, itB.x, t);
            t = fmaf(a01, nBy, t); t = fmaf(b01, fBy, t); t = fmaf(c01, itB.y, t);
            t = fmaf(a02, nBz, t); t = fmaf(b02, fBz, t); t = fmaf(c02, itB.z, t);
            t = fmaf(a03, nBw, t); t = fmaf(b03, fBw, t); t = fmaf(c03, itB.w, t);
            PB0 = t;
            t = a10 * nBx; t = fmaf(b10, fBx, t); t = fmaf(c10, itB.x, t);
            t = fmaf(a11, nBy, t); t = fmaf(b11, fBy, t); t = fmaf(c11, itB.y, t);
            t = fmaf(a12, nBz, t); t = fmaf(b12, fBz, t); t = fmaf(c12, itB.z, t);
            t = fmaf(a13, nBw, t); t = fmaf(b13, fBw, t); t = fmaf(c13, itB.w, t);
            PB1 = t;
        }

        // Select-free MLP reduce (xor 4, 2, 1): lane owns H_{j0} per pair.
        float hA = PA0 + __shfl_xor_sync(FULL, PA1, 4);
        float hB = PB0 + __shfl_xor_sync(FULL, PB1, 4);
        hA += __shfl_xor_sync(FULL, hA, 2);
        hB += __shfl_xor_sync(FULL, hB, 2);
        hA += __shfl_xor_sync(FULL, hA, 1);
        hB += __shfl_xor_sync(FULL, hB, 1);

        // Output layer, combined half-split tail reduce for both pairs.
        const float tA = w2c * fmaxf(hA + b1c, 0.f);
        const float tB = w2c * fmaxf(hB + b1c, 0.f);
        float x    = half ? tB : tA;
        float send = half ? tA : tB;
        x += __shfl_xor_sync(FULL, send, 16);
        x += __shfl_xor_sync(FULL, x, 8);
        x += __shfl_xor_sync(FULL, x, 4);
        x += __shfl_xor_sync(FULL, x, 2);
        x += __shfl_xor_sync(FULL, x, 1);
        // lanes 0-15 hold tvA, lanes 16-31 hold tvB.

        const float y  = 1.f / (1.f + __expf(-(x + b2v)));
        const float yB = __shfl_sync(FULL, y, 16);
        if (lane == 0) {
            if (bB != bA) {
                *(float2*)(out + base) = make_float2(y, yB);
            } else {
                out[base] = y;
            }
        }
    }
}

// ---------------------------------------------------------------------------
extern "C" void kernel_launch(void* const* d_in, const int* in_sizes, int n_in,
                              void* d_out, int out_size)
{
    const int*   item_inputs = (const int*)  d_in[0];
    const int*   member_ids  = (const int*)  d_in[1];
    const void*  member_mask =               d_in[2];
    const float* user_table  = (const float*)d_in[3];
    const float* item_table  = (const float*)d_in[4];
    const float* W_bil       = (const float*)d_in[5];
    const float* b_bil       = (const float*)d_in[6];
    const float* W1          = (const float*)d_in[7];
    const float* b1          = (const float*)d_in[8];
    const float* W2          = (const float*)d_in[9];
    const float* b2          = (const float*)d_in[10];
    float* out = (float*)d_out;

    const int B  = in_sizes[0];
    int NI = in_sizes[4] / 32;
    if (NI > 50000) NI = 50000;   // g_vtab capacity (problem spec: NI = 50000)

    vtab_kernel<<<(NI + 7) / 8, 256>>>(W_bil, item_table,
                                       (const unsigned int*)member_mask, NI);
    bilinear_main_kernel<<<444, 256>>>(item_inputs, member_ids, member_mask,
                                       user_table, item_table,
                                       b_bil, W1, b1, W2, b2, out, B);
}

// round 8
// speedup vs baseline: 1.5088x; 1.2187x over previous
#include <cuda_runtime.h>

#define FULL 0xFFFFFFFFu

// Precomputed v[i,d] = sum_e W_bil[d,e] * item_table[i,e]  (NI=50000, D=32)
__device__ float g_vtab[50000 * 32];
// Mask dtype mode: 0 = int32, 1 = float32, 2 = uint8 (packed bytes)
__device__ int g_mask_mode;

// ---------------------------------------------------------------------------
// Precompute kernel: one warp per item row. W_bil transposed into padded smem.
// Thread (0,0) sniffs the member_mask dtype (mask[0,0] is guaranteed true).
// ---------------------------------------------------------------------------
__global__ void __launch_bounds__(256) vtab_kernel(
    const float* __restrict__ W_bil,
    const float* __restrict__ item_table,
    const unsigned int* __restrict__ mask_words,
    int NI)
{
    __shared__ float WT[32 * 33];
    int t = threadIdx.x;

    if (blockIdx.x == 0 && t == 0) {
        unsigned int w0 = mask_words[0];
        int mode;
        if (w0 == 1u)               mode = 0;  // int32 bool
        else if (w0 == 0x3F800000u) mode = 1;  // float32 bool
        else                        mode = 2;  // uint8 bytes
        g_mask_mode = mode;
    }

    for (int k = t; k < 1024; k += blockDim.x) {
        int d = k >> 5, e = k & 31;
        WT[e * 33 + d] = W_bil[k];
    }
    __syncthreads();

    int warp = t >> 5, lane = t & 31;
    int i = blockIdx.x * (blockDim.x >> 5) + warp;
    if (i >= NI) return;

    float x = item_table[i * 32 + lane];
    float v = 0.f;
    #pragma unroll
    for (int e = 0; e < 32; e++) {
        v = fmaf(WT[e * 33 + lane], __shfl_sync(FULL, x, e), v);
    }
    g_vtab[i * 32 + lane] = v;
}

__device__ __forceinline__ float dot4(const float4 a, const float4 b) {
    return fmaf(a.x, b.x, fmaf(a.y, b.y, fmaf(a.z, b.z, a.w * b.w)));
}

// ---------------------------------------------------------------------------
// Main kernel: one warp, TWO pairs per iteration (ILP=2). lane = (g = lane>>3
// member-group, c = lane&7 float4 dim-chunk). Slot i = member 4i+g uniformly
// on all lanes, so each member LDG.128 touches only 4 cache lines (one per g)
// -> 4 L1 wavefronts. Scores are reduced replicated (every lane gets all 4
// slot scores); mask bits ride in the id sign bit. MLP uses smem-resident W1
// with select-free XOR-permuted unit assignment.
// ---------------------------------------------------------------------------
__global__ void __launch_bounds__(256, 3) bilinear_main_kernel(
    const int*           __restrict__ item_inputs,
    const int*           __restrict__ member_ids,
    const void*          __restrict__ member_mask,
    const float*         __restrict__ user_table,
    const float*         __restrict__ item_table,
    const float*         __restrict__ b_bil,
    const float*         __restrict__ W1,
    const float*         __restrict__ b1,
    const float*         __restrict__ W2,
    const float*         __restrict__ b2,
    float*               __restrict__ out,
    int B)
{
    __shared__ float w1s[768];      // W1 [8][96]
    for (int k = threadIdx.x; k < 768; k += 256) w1s[k] = W1[k];
    __syncthreads();

    const int lane   = threadIdx.x & 31;
    const int warp   = (blockIdx.x * blockDim.x + threadIdx.x) >> 5;
    const int nwarps = (gridDim.x * blockDim.x) >> 5;

    const int g   = lane >> 3;        // member group 0..3
    const int c   = lane & 7;         // dim chunk 0..7 (dims 4c..4c+3)
    const int rho = (c >> 2) & 1;

    const int j0 = 2 * g + rho;       // owned MLP unit
    const int j1 = 2 * g + (1 ^ rho);

    const float b1c = b1[j0];
    const float w2c = W2[j0] * 0.25f;
    const float bb  = b_bil[0];
    const float b2v = b2[0];
    const int   mmode = g_mask_mode;
    const int   half  = lane >> 4;    // 0 -> pair A, 1 -> pair B
    const int   memi  = lane & 15;    // member index this lane loads id/mask for

    const unsigned w1_0 = (unsigned)__cvta_generic_to_shared(&w1s[j0 * 96 + 4 * c]);
    const unsigned w1_1 = (unsigned)__cvta_generic_to_shared(&w1s[j1 * 96 + 4 * c]);

    const float4* __restrict__ ut4  = (const float4*)user_table;
    const float4* __restrict__ it4p = (const float4*)item_table;
    const float4* __restrict__ vt4p = (const float4*)g_vtab;

    for (int base = 2 * warp; base < B; base += 2 * nwarps) {
        const int bA = base;
        const int bB = (base + 1 < B) ? base + 1 : base;

        const int itmA = item_inputs[bA];
        const int itmB = item_inputs[bB];
        const float4 itA = it4p[itmA * 8 + c];
        const float4 vA  = vt4p[itmA * 8 + c];
        const float4 itB = it4p[itmB * 8 + c];
        const float4 vB  = vt4p[itmB * 8 + c];

        // One 128B load serves both pairs' member ids (lanes 0-15: A, 16-31: B)
        const int bH  = half ? bB : bA;
        const int mid = member_ids[bH * 16 + memi];

        // Mask bit for member memi of pair bH, packed into the id sign bit.
        int mkbit;
        if (mmode == 0) {
            mkbit = (((const int*)member_mask)[bH * 16 + memi] != 0);
        } else if (mmode == 1) {
            mkbit = (((const float*)member_mask)[bH * 16 + memi] != 0.f);
        } else {
            mkbit = (((const unsigned char*)member_mask)[bH * 16 + memi] != 0);
        }
        const int pk = mid | (mkbit << 31);

        // Distribute packed id+mask: slot i = member 4i+g (uniform across c).
        const int pA0 = __shfl_sync(FULL, pk,      4 * 0 + g);
        const int pA1 = __shfl_sync(FULL, pk,      4 * 1 + g);
        const int pA2 = __shfl_sync(FULL, pk,      4 * 2 + g);
        const int pA3 = __shfl_sync(FULL, pk,      4 * 3 + g);
        const int pB0 = __shfl_sync(FULL, pk, 16 + 4 * 0 + g);
        const int pB1 = __shfl_sync(FULL, pk, 16 + 4 * 1 + g);
        const int pB2 = __shfl_sync(FULL, pk, 16 + 4 * 2 + g);
        const int pB3 = __shfl_sync(FULL, pk, 16 + 4 * 3 + g);

        // Gathers: per LDG, the 32 lanes cover 4 rows x full 128B line.
        const float4 mA0 = ut4[(pA0 & 0x7FFFFFFF) * 8 + c];
        const float4 mA1 = ut4[(pA1 & 0x7FFFFFFF) * 8 + c];
        const float4 mA2 = ut4[(pA2 & 0x7FFFFFFF) * 8 + c];
        const float4 mA3 = ut4[(pA3 & 0x7FFFFFFF) * 8 + c];
        const float4 mB0 = ut4[(pB0 & 0x7FFFFFFF) * 8 + c];
        const float4 mB1 = ut4[(pB1 & 0x7FFFFFFF) * 8 + c];
        const float4 mB2 = ut4[(pB2 & 0x7FFFFFFF) * 8 + c];
        const float4 mB3 = ut4[(pB3 & 0x7FFFFFFF) * 8 + c];

        // Score partials and replicated reduce over the 8-lane c-group.
        float sA0 = dot4(mA0, vA), sA1 = dot4(mA1, vA);
        float sA2 = dot4(mA2, vA), sA3 = dot4(mA3, vA);
        float sB0 = dot4(mB0, vB), sB1 = dot4(mB1, vB);
        float sB2 = dot4(mB2, vB), sB3 = dot4(mB3, vB);

        sA0 += __shfl_xor_sync(FULL, sA0, 4); sA1 += __shfl_xor_sync(FULL, sA1, 4);
        sA2 += __shfl_xor_sync(FULL, sA2, 4); sA3 += __shfl_xor_sync(FULL, sA3, 4);
        sB0 += __shfl_xor_sync(FULL, sB0, 4); sB1 += __shfl_xor_sync(FULL, sB1, 4);
        sB2 += __shfl_xor_sync(FULL, sB2, 4); sB3 += __shfl_xor_sync(FULL, sB3, 4);
        sA0 += __shfl_xor_sync(FULL, sA0, 2); sA1 += __shfl_xor_sync(FULL, sA1, 2);
        sA2 += __shfl_xor_sync(FULL, sA2, 2); sA3 += __shfl_xor_sync(FULL, sA3, 2);
        sB0 += __shfl_xor_sync(FULL, sB0, 2); sB1 += __shfl_xor_sync(FULL, sB1, 2);
        sB2 += __shfl_xor_sync(FULL, sB2, 2); sB3 += __shfl_xor_sync(FULL, sB3, 2);
        sA0 += __shfl_xor_sync(FULL, sA0, 1); sA1 += __shfl_xor_sync(FULL, sA1, 1);
        sA2 += __shfl_xor_sync(FULL, sA2, 1); sA3 += __shfl_xor_sync(FULL, sA3, 1);
        sB0 += __shfl_xor_sync(FULL, sB0, 1); sB1 += __shfl_xor_sync(FULL, sB1, 1);
        sB2 += __shfl_xor_sync(FULL, sB2, 1); sB3 += __shfl_xor_sync(FULL, sB3, 1);

        // Weights: w_i = mask_i ? (S_i + bias) : 0, locally on every lane.
        const float wA0 = (pA0 < 0) ? (sA0 + bb) : 0.f;
        const float wA1 = (pA1 < 0) ? (sA1 + bb) : 0.f;
        const float wA2 = (pA2 < 0) ? (sA2 + bb) : 0.f;
        const float wA3 = (pA3 < 0) ? (sA3 + bb) : 0.f;
        const float wB0 = (pB0 < 0) ? (sB0 + bb) : 0.f;
        const float wB1 = (pB1 < 0) ? (sB1 + bb) : 0.f;
        const float wB2 = (pB2 < 0) ? (sB2 + bb) : 0.f;
        const float wB3 = (pB3 < 0) ? (sB3 + bb) : 0.f;

        // fu partials over this lane's 4 members, then reduce over g.
        float fAx = wA0 * mA0.x, fAy = wA0 * mA0.y, fAz = wA0 * mA0.z, fAw = wA0 * mA0.w;
        fAx = fmaf(wA1, mA1.x, fAx); fAy = fmaf(wA1, mA1.y, fAy);
        fAz = fmaf(wA1, mA1.z, fAz); fAw = fmaf(wA1, mA1.w, fAw);
        fAx = fmaf(wA2, mA2.x, fAx); fAy = fmaf(wA2, mA2.y, fAy);
        fAz = fmaf(wA2, mA2.z, fAz); fAw = fmaf(wA2, mA2.w, fAw);
        fAx = fmaf(wA3, mA3.x, fAx); fAy = fmaf(wA3, mA3.y, fAy);
        fAz = fmaf(wA3, mA3.z, fAz); fAw = fmaf(wA3, mA3.w, fAw);

        float fBx = wB0 * mB0.x, fBy = wB0 * mB0.y, fBz = wB0 * mB0.z, fBw = wB0 * mB0.w;
        fBx = fmaf(wB1, mB1.x, fBx); fBy = fmaf(wB1, mB1.y, fBy);
        fBz = fmaf(wB1, mB1.z, fBz); fBw = fmaf(wB1, mB1.w, fBw);
        fBx = fmaf(wB2, mB2.x, fBx); fBy = fmaf(wB2, mB2.y, fBy);
        fBz = fmaf(wB2, mB2.z, fBz); fBw = fmaf(wB2, mB2.w, fBw);
        fBx = fmaf(wB3, mB3.x, fBx); fBy = fmaf(wB3, mB3.y, fBy);
        fBz = fmaf(wB3, mB3.z, fBz); fBw = fmaf(wB3, mB3.w, fBw);

        fAx += __shfl_xor_sync(FULL, fAx, 8);  fAy += __shfl_xor_sync(FULL, fAy, 8);
        fAz += __shfl_xor_sync(FULL, fAz, 8);  fAw += __shfl_xor_sync(FULL, fAw, 8);
        fBx += __shfl_xor_sync(FULL, fBx, 8);  fBy += __shfl_xor_sync(FULL, fBy, 8);
        fBz += __shfl_xor_sync(FULL, fBz, 8);  fBw += __shfl_xor_sync(FULL, fBw, 8);
        fAx += __shfl_xor_sync(FULL, fAx, 16); fAy += __shfl_xor_sync(FULL, fAy, 16);
        fAz += __shfl_xor_sync(FULL, fAz, 16); fAw += __shfl_xor_sync(FULL, fAw, 16);
        fBx += __shfl_xor_sync(FULL, fBx, 16); fBy += __shfl_xor_sync(FULL, fBy, 16);
        fBz += __shfl_xor_sync(FULL, fBz, 16); fBw += __shfl_xor_sync(FULL, fBw, 16);

        // MLP layer 1. ne = fu*it.
        const float nAx = fAx * itA.x, nAy = fAy * itA.y;
        const float nAz = fAz * itA.z, nAw = fAw * itA.w;
        const float nBx = fBx * itB.x, nBy = fBy * itB.y;
        const float nBz = fBz * itB.z, nBw = fBw * itB.w;

        // Reload W1 slices from smem each iteration (volatile: not hoisted).
        float a00,a01,a02,a03, b00,b01,b02,b03, c00,c01,c02,c03;
        float a10,a11,a12,a13, b10,b11,b12,b13, c10,c11,c12,c13;
        asm volatile("ld.shared.v4.f32 {%0,%1,%2,%3},[%4];"
            : "=f"(a00),"=f"(a01),"=f"(a02),"=f"(a03) : "r"(w1_0));
        asm volatile("ld.shared.v4.f32 {%0,%1,%2,%3},[%4];"
            : "=f"(b00),"=f"(b01),"=f"(b02),"=f"(b03) : "r"(w1_0 + 128));
        asm volatile("ld.shared.v4.f32 {%0,%1,%2,%3},[%4];"
            : "=f"(c00),"=f"(c01),"=f"(c02),"=f"(c03) : "r"(w1_0 + 256));
        asm volatile("ld.shared.v4.f32 {%0,%1,%2,%3},[%4];"
            : "=f"(a10),"=f"(a11),"=f"(a12),"=f"(a13) : "r"(w1_1));
        asm volatile("ld.shared.v4.f32 {%0,%1,%2,%3},[%4];"
            : "=f"(b10),"=f"(b11),"=f"(b12),"=f"(b13) : "r"(w1_1 + 128));
        asm volatile("ld.shared.v4.f32 {%0,%1,%2,%3},[%4];"
            : "=f"(c10),"=f"(c11),"=f"(c12),"=f"(c13) : "r"(w1_1 + 256));

        float PA0, PA1, PB0, PB1;
        {
            float t;
            t = a00 * nAx; t = fmaf(b00, fAx, t); t = fmaf(c00, itA.x, t);
            t = fmaf(a01, nAy, t); t = fmaf(b01, fAy, t); t = fmaf(c01, itA.y, t);
            t = fmaf(a02, nAz, t); t = fmaf(b02, fAz, t); t = fmaf(c02, itA.z, t);
            t = fmaf(a03, nAw, t); t = fmaf(b03, fAw, t); t = fmaf(c03, itA.w, t);
            PA0 = t;
            t = a10 * nAx; t = fmaf(b10, fAx, t); t = fmaf(c10, itA.x, t);
            t = fmaf(a11, nAy, t); t = fmaf(b11, fAy, t); t = fmaf(c11, itA.y, t);
            t = fmaf(a12, nAz, t); t = fmaf(b12, fAz, t); t = fmaf(c12, itA.z, t);
            t = fmaf(a13, nAw, t); t = fmaf(b13, fAw, t); t = fmaf(c13, itA.w, t);
            PA1 = t;
            t = a00 * nBx; t = fmaf(b00, fBx, t); t = fmaf(c00, itB.x, t);
            t = fmaf(a01, nBy, t); t = fmaf(b01, fBy, t); t = fmaf(c01, itB.y, t);
            t = fmaf(a02, nBz, t); t = fmaf(b02, fBz, t); t = fmaf(c02, itB.z, t);
            t = fmaf(a03, nBw, t); t = fmaf(b03, fBw, t); t = fmaf(c03, itB.w, t);
            PB0 = t;
            t = a10 * nBx; t = fmaf(b10, fBx, t); t = fmaf(c10, itB.x, t);
            t = fmaf(a11, nBy, t); t = fmaf(b11, fBy, t); t = fmaf(c11, itB.y, t);
            t = fmaf(a12, nBz, t); t = fmaf(b12, fBz, t); t = fmaf(c12, itB.z, t);
            t = fmaf(a13, nBw, t); t = fmaf(b13, fBw, t); t = fmaf(c13, itB.w, t);
            PB1 = t;
        }

        // Select-free MLP reduce (xor 4, 2, 1): lane owns H_{j0} per pair.
        float hA = PA0 + __shfl_xor_sync(FULL, PA1, 4);
        float hB = PB0 + __shfl_xor_sync(FULL, PB1, 4);
        hA += __shfl_xor_sync(FULL, hA, 2);
        hB += __shfl_xor_sync(FULL, hB, 2);
        hA += __shfl_xor_sync(FULL, hA, 1);
        hB += __shfl_xor_sync(FULL, hB, 1);

        // Output layer, combined half-split tail reduce for both pairs.
        const float tA = w2c * fmaxf(hA + b1c, 0.f);
        const float tB = w2c * fmaxf(hB + b1c, 0.f);
        float x    = half ? tB : tA;
        float send = half ? tA : tB;
        x += __shfl_xor_sync(FULL, send, 16);
        x += __shfl_xor_sync(FULL, x, 8);
        x += __shfl_xor_sync(FULL, x, 4);
        x += __shfl_xor_sync(FULL, x, 2);
        x += __shfl_xor_sync(FULL, x, 1);
        // lanes 0-15 hold tvA, lanes 16-31 hold tvB.

        const float y  = 1.f / (1.f + __expf(-(x + b2v)));
        const float yB = __shfl_sync(FULL, y, 16);
        if (lane == 0) {
            if (bB != bA) {
                *(float2*)(out + base) = make_float2(y, yB);
            } else {
                out[base] = y;
            }
        }
    }
}

// ---------------------------------------------------------------------------
extern "C" void kernel_launch(void* const* d_in, const int* in_sizes, int n_in,
                              void* d_out, int out_size)
{
    const int*   item_inputs = (const int*)  d_in[0];
    const int*   member_ids  = (const int*)  d_in[1];
    const void*  member_mask =               d_in[2];
    const float* user_table  = (const float*)d_in[3];
    const float* item_table  = (const float*)d_in[4];
    const float* W_bil       = (const float*)d_in[5];
    const float* b_bil       = (const float*)d_in[6];
    const float* W1          = (const float*)d_in[7];
    const float* b1          = (const float*)d_in[8];
    const float* W2          = (const float*)d_in[9];
    const float* b2          = (const float*)d_in[10];
    float* out = (float*)d_out;

    const int B  = in_sizes[0];
    int NI = in_sizes[4] / 32;
    if (NI > 50000) NI = 50000;   // g_vtab capacity (problem spec: NI = 50000)

    vtab_kernel<<<(NI + 7) / 8, 256>>>(W_bil, item_table,
                                       (const unsigned int*)member_mask, NI);
    bilinear_main_kernel<<<444, 256>>>(item_inputs, member_ids, member_mask,
                                       user_table, item_table,
                                       b_bil, W1, b1, W2, b2, out, B);
}